// round 5
// baseline (speedup 1.0000x reference)
#include <cuda_runtime.h>
#include <cuda_fp16.h>
#include <cstdint>

#define NF      2560
#define TW      16
#define HWDIM   9216
#define BT      1920
#define T_LEN   240
#define BATCH   8

#define BM      128     // bt rows per CTA (M)
#define BNF     128     // filters per CTA (N)
#define KC      64      // K elements per stage
#define NCHUNK  144     // 9216/64
#define PADROWB 144     // bytes per smem row (64 halves = 128B + 16B pad)
#define OFF_A   0
#define OFF_B   (128 * PADROWB)          // 18432
#define STG_BYTES (256 * PADROWB)        // 36864
#define SMEM_DYN  (3 * STG_BYTES)        // 110592

// fp16 copies of inputs (filled by convert kernel)
__device__ __half x_h[BT * HWDIM];
__device__ __half ws_h[NF * HWDIM];
__device__ __half wc_h[NF * HWDIM];
// intermediate g_sin / g_cos, layout [bt][f]
__device__ float g_buf0[BT * NF];
__device__ float g_buf1[BT * NF];

// ---------------------------------------------------------------------------
__device__ __forceinline__ unsigned smem_u32(const void* p) {
    return (unsigned)__cvta_generic_to_shared(p);
}
__device__ __forceinline__ void cp_async16(unsigned saddr, const void* gaddr) {
    asm volatile("cp.async.cg.shared.global [%0], [%1], 16;\n" :: "r"(saddr), "l"(gaddr));
}
__device__ __forceinline__ void ldsm_x4(uint32_t* r, unsigned addr) {
    asm volatile("ldmatrix.sync.aligned.m8n8.x4.shared.b16 {%0,%1,%2,%3}, [%4];"
                 : "=r"(r[0]), "=r"(r[1]), "=r"(r[2]), "=r"(r[3]) : "r"(addr));
}
__device__ __forceinline__ void mma_fp16(float* c, const uint32_t* a, const uint32_t* b) {
    asm volatile(
        "mma.sync.aligned.m16n8k16.row.col.f32.f16.f16.f32 "
        "{%0,%1,%2,%3}, {%4,%5,%6,%7}, {%8,%9}, {%0,%1,%2,%3};\n"
        : "+f"(c[0]), "+f"(c[1]), "+f"(c[2]), "+f"(c[3])
        : "r"(a[0]), "r"(a[1]), "r"(a[2]), "r"(a[3]), "r"(b[0]), "r"(b[1]));
}

// ---------------------------------------------------------------------------
// Kernel 0: fp32 -> fp16 conversion (vectorized)
// ---------------------------------------------------------------------------
__global__ void __launch_bounds__(256)
f2h_kernel(const float* __restrict__ src, __half* __restrict__ dst, int n4) {
    int i = blockIdx.x * 256 + threadIdx.x;
    if (i < n4) {
        float4 v = reinterpret_cast<const float4*>(src)[i];
        reinterpret_cast<__half2*>(dst)[2 * i]     = __floats2half2_rn(v.x, v.y);
        reinterpret_cast<__half2*>(dst)[2 * i + 1] = __floats2half2_rn(v.z, v.w);
    }
}

// ---------------------------------------------------------------------------
// Kernel 1: spatial GEMM, fp16 mma.sync, KC=64, 3-stage cp.async, 2 CTAs/SM,
// ONE __syncthreads per K-chunk.
//   g[m, f] = sum_k x[m,k] * w[f,k]
// Block tile 128(m) x 128(f), 256 threads, warp tile 64m x 32f.
// blockIdx.z: 0 -> ws_h -> g_buf0, 1 -> wc_h -> g_buf1.
// ---------------------------------------------------------------------------
__global__ void __launch_bounds__(256, 2)
spatial_gemm_fp16(int dummy) {
    extern __shared__ __align__(1024) char smem[];
    const unsigned smem_base = smem_u32(smem);
    const int tid = threadIdx.x;
    const int n0 = blockIdx.x * BNF;   // filter base
    const int m0 = blockIdx.y * BM;    // bt base
    const __half* wmat = blockIdx.z ? wc_h : ws_h;
    float* gout = blockIdx.z ? g_buf1 : g_buf0;

    const int lane = tid & 31;
    const int warp = tid >> 5;
    const int wm = (warp & 1) * 64;
    const int wn = (warp >> 1) * 32;

    float acc[4][4][4];
    #pragma unroll
    for (int i = 0; i < 4; i++)
        #pragma unroll
        for (int j = 0; j < 4; j++)
            #pragma unroll
            for (int k = 0; k < 4; k++) acc[i][j][k] = 0.f;

    // loader: row = tid>>1 (0..127), 4 x 16B segments per thread per array
    const int lrow = tid >> 1;
    const int scol = (tid & 1) * 32;   // starting half within the 64-half row
    const __half* ga = x_h  + (size_t)(m0 + lrow) * HWDIM + scol;
    const __half* gb = wmat + (size_t)(n0 + lrow) * HWDIM + scol;
    const unsigned lsm = smem_base + lrow * PADROWB + scol * 2;

    auto load_stage = [&](int kt, int slot) {
        const unsigned sb = lsm + slot * STG_BYTES;
        const __half* pa = ga + kt * KC;
        const __half* pb = gb + kt * KC;
        #pragma unroll
        for (int i = 0; i < 4; i++) {
            cp_async16(sb + OFF_A + i * 16, pa + i * 8);
            cp_async16(sb + OFF_B + i * 16, pb + i * 8);
        }
        asm volatile("cp.async.commit_group;\n");
    };

    // ldmatrix per-lane byte offsets within a stage
    const int mrow = wm + (lane & 7) + 8 * ((lane >> 3) & 1);
    const int akb  = (lane >> 4) * 16;
    unsigned aoff[4];
    #pragma unroll
    for (int mt = 0; mt < 4; mt++) aoff[mt] = (mrow + mt * 16) * PADROWB + akb;

    const int nrow = wn + (lane & 7) + 8 * (lane >> 4);
    const int bkb  = ((lane >> 3) & 1) * 16;
    unsigned boff[2];
    #pragma unroll
    for (int p = 0; p < 2; p++) boff[p] = (nrow + p * 16) * PADROWB + bkb;

    // prologue
    load_stage(0, 0);
    load_stage(1, 1);

    for (int kt = 0; kt < NCHUNK; kt++) {
        if (kt < NCHUNK - 1) asm volatile("cp.async.wait_group 1;\n");
        else                 asm volatile("cp.async.wait_group 0;\n");
        __syncthreads();   // stage kt ready; all warps done with slot (kt-1)%3
        if (kt + 2 < NCHUNK) load_stage(kt + 2, (kt + 2) % 3);

        const unsigned sb = smem_base + (kt % 3) * STG_BYTES;
        #pragma unroll
        for (int kk = 0; kk < 4; kk++) {
            const unsigned kb = kk * 32;
            uint32_t a[4][4], b[2][4];
            #pragma unroll
            for (int mt = 0; mt < 4; mt++) ldsm_x4(a[mt], sb + OFF_A + aoff[mt] + kb);
            #pragma unroll
            for (int p = 0; p < 2; p++) ldsm_x4(b[p], sb + OFF_B + boff[p] + kb);
            #pragma unroll
            for (int mt = 0; mt < 4; mt++)
                #pragma unroll
                for (int nt = 0; nt < 4; nt++)
                    mma_fp16(acc[mt][nt], a[mt], &b[nt >> 1][(nt & 1) * 2]);
        }
        // no bottom sync: next iter's top __syncthreads provides the WAR guard
    }

    // epilogue
    #pragma unroll
    for (int mt = 0; mt < 4; mt++) {
        #pragma unroll
        for (int nt = 0; nt < 4; nt++) {
            int m = m0 + wm + mt * 16 + (lane >> 2);
            int n = n0 + wn + nt * 8 + (lane & 3) * 2;
            *reinterpret_cast<float2*>(&gout[(size_t)m * NF + n]) =
                make_float2(acc[mt][nt][0], acc[mt][nt][1]);
            *reinterpret_cast<float2*>(&gout[(size_t)(m + 8) * NF + n]) =
                make_float2(acc[mt][nt][2], acc[mt][nt][3]);
        }
    }
}

// ---------------------------------------------------------------------------
// Kernel 2: depthwise temporal convs + energy. Ring-buffer sliding window,
// T split into 5 chunks of 48.
// ---------------------------------------------------------------------------
__global__ void __launch_bounds__(256)
temporal_kernel(const float* __restrict__ wt_sin_g,
                const float* __restrict__ wt_cos_g,
                float* __restrict__ out) {
    const int f = blockIdx.x * 256 + threadIdx.x;
    const int b = blockIdx.y;
    const int t0 = blockIdx.z * 48;

    float wts[TW], wtc[TW];
    #pragma unroll
    for (int j = 0; j < TW; j++) {
        wts[j] = wt_sin_g[f * TW + j];
        wtc[j] = wt_cos_g[f * TW + j];
    }

    const float* gs = g_buf0 + (size_t)b * T_LEN * NF + f;
    const float* gc = g_buf1 + (size_t)b * T_LEN * NF + f;
    float* op = out + (size_t)b * T_LEN * NF + f;

    float rs[TW], rc[TW];
    #pragma unroll
    for (int j = 0; j < TW; j++) {
        int t = t0 - 8 + j;
        int i = t & 15;
        rs[i] = (t >= 0) ? gs[t * NF] : 0.f;
        rc[i] = (t >= 0) ? gc[t * NF] : 0.f;
    }

    #pragma unroll 16
    for (int tt = 0; tt < 48; tt++) {
        const int t = t0 + tt;
        float t1 = 0.f, t2 = 0.f, t3 = 0.f, t4 = 0.f;
        #pragma unroll
        for (int j = 0; j < TW; j++) {
            int i = (tt - 8 + j) & 15;
            t1 += rs[i] * wtc[j];
            t2 += rc[i] * wts[j];
            t3 += rc[i] * wtc[j];
            t4 += rs[i] * wts[j];
        }
        float resp_s = t1 + t2;
        float resp_c = t3 - t4;
        float v = resp_s * resp_s + resp_c * resp_c;
        op[t * NF] = logf(sqrtf(v) + 1e-5f);

        int tn = t + 8;
        int i = tn & 15;
        rs[i] = (tn < T_LEN) ? gs[tn * NF] : 0.f;
        rc[i] = (tn < T_LEN) ? gc[tn * NF] : 0.f;
    }
}

extern "C" void kernel_launch(void* const* d_in, const int* in_sizes, int n_in,
                              void* d_out, int out_size) {
    const float* x       = (const float*)d_in[0];
    const float* w_s_sin = (const float*)d_in[1];
    const float* w_s_cos = (const float*)d_in[2];
    const float* w_t_sin = (const float*)d_in[3];
    const float* w_t_cos = (const float*)d_in[4];
    float* out = (float*)d_out;

    __half *dx, *dws, *dwc;
    cudaGetSymbolAddress((void**)&dx,  x_h);
    cudaGetSymbolAddress((void**)&dws, ws_h);
    cudaGetSymbolAddress((void**)&dwc, wc_h);

    const int nx4 = BT * HWDIM / 4;
    const int nw4 = NF * HWDIM / 4;
    f2h_kernel<<<(nx4 + 255) / 256, 256>>>(x, dx, nx4);
    f2h_kernel<<<(nw4 + 255) / 256, 256>>>(w_s_sin, dws, nw4);
    f2h_kernel<<<(nw4 + 255) / 256, 256>>>(w_s_cos, dwc, nw4);

    cudaFuncSetAttribute(spatial_gemm_fp16,
                         cudaFuncAttributeMaxDynamicSharedMemorySize, SMEM_DYN);

    dim3 g1(NF / BNF, BT / BM, 2);     // (20, 15, 2) = 600 CTAs, 2/SM
    spatial_gemm_fp16<<<g1, 256, SMEM_DYN>>>(0);

    dim3 g2(NF / 256, BATCH, T_LEN / 48);   // (10, 8, 5)
    temporal_kernel<<<g2, 256>>>(w_t_sin, w_t_cos, out);
}

// round 6
// speedup vs baseline: 1.2520x; 1.2520x over previous
#include <cuda_runtime.h>
#include <cuda_fp16.h>
#include <cstdint>

#define NF      2560
#define TW      16
#define HWDIM   9216
#define BT      1920
#define T_LEN   240
#define BATCH   8

#define BM      128     // bt rows per CTA (M)
#define BNF     128     // filters per CTA (N)
#define KC      32      // K elements per stage
#define KHALF   4608    // HWDIM / 2
#define NCHUNK  144     // KHALF / KC
#define PADROWB 80      // bytes per smem row (32 halves = 64B + 16B pad)
#define OFF_A   0
#define OFF_B   (128 * PADROWB)          // 10240
#define STG_BYTES (256 * PADROWB)        // 20480
#define SMEM_DYN  (3 * STG_BYTES)        // 61440

// fp16 copies of inputs (filled by convert kernel)
__device__ __half x_h[BT * HWDIM];
__device__ __half ws_h[NF * HWDIM];
__device__ __half wc_h[NF * HWDIM];
// split-K partials: [variant*2 + khalf][bt][f]
//   0: sin k0   1: sin k1   2: cos k0   3: cos k1
__device__ float g_buf[4][BT * NF];

// ---------------------------------------------------------------------------
__device__ __forceinline__ unsigned smem_u32(const void* p) {
    return (unsigned)__cvta_generic_to_shared(p);
}
__device__ __forceinline__ void cp_async16(unsigned saddr, const void* gaddr) {
    asm volatile("cp.async.cg.shared.global [%0], [%1], 16;\n" :: "r"(saddr), "l"(gaddr));
}
__device__ __forceinline__ void ldsm_x4(uint32_t* r, unsigned addr) {
    asm volatile("ldmatrix.sync.aligned.m8n8.x4.shared.b16 {%0,%1,%2,%3}, [%4];"
                 : "=r"(r[0]), "=r"(r[1]), "=r"(r[2]), "=r"(r[3]) : "r"(addr));
}
__device__ __forceinline__ void mma_fp16(float* c, const uint32_t* a, const uint32_t* b) {
    asm volatile(
        "mma.sync.aligned.m16n8k16.row.col.f32.f16.f16.f32 "
        "{%0,%1,%2,%3}, {%4,%5,%6,%7}, {%8,%9}, {%0,%1,%2,%3};\n"
        : "+f"(c[0]), "+f"(c[1]), "+f"(c[2]), "+f"(c[3])
        : "r"(a[0]), "r"(a[1]), "r"(a[2]), "r"(a[3]), "r"(b[0]), "r"(b[1]));
}

// ---------------------------------------------------------------------------
// Kernel 0: fp32 -> fp16 conversion for x, w_s_sin, w_s_cos in ONE launch.
// ---------------------------------------------------------------------------
#define NX4 (BT * HWDIM / 4)        // 4423680
#define NW4 (NF * HWDIM / 4)        // 5898240
__global__ void __launch_bounds__(256)
f2h_all_kernel(const float* __restrict__ x,
               const float* __restrict__ wsin,
               const float* __restrict__ wcos) {
    int i = blockIdx.x * 256 + threadIdx.x;
    const float* src;
    __half* dst;
    int j;
    if (i < NX4)                 { src = x;    dst = x_h;  j = i; }
    else if (i < NX4 + NW4)      { src = wsin; dst = ws_h; j = i - NX4; }
    else if (i < NX4 + 2 * NW4)  { src = wcos; dst = wc_h; j = i - NX4 - NW4; }
    else return;
    float4 v = reinterpret_cast<const float4*>(src)[j];
    reinterpret_cast<__half2*>(dst)[2 * j]     = __floats2half2_rn(v.x, v.y);
    reinterpret_cast<__half2*>(dst)[2 * j + 1] = __floats2half2_rn(v.z, v.w);
}

// ---------------------------------------------------------------------------
// Kernel 1: spatial GEMM, fp16 mma.sync, KC=32, 3-stage cp.async, 2 CTAs/SM,
// split-K x2 (round-4 loop structure, proven fastest).
//   g_buf[z][m, f] = sum_{k in half z&1} x[m,k] * w_{z>>1}[f,k]
// Block tile 128(m) x 128(f), 256 threads, warp tile 64m x 32f.
// ---------------------------------------------------------------------------
__global__ void __launch_bounds__(256, 2)
spatial_gemm_fp16(int dummy) {
    extern __shared__ __align__(1024) char smem[];
    const unsigned smem_base = smem_u32(smem);
    const int tid = threadIdx.x;
    const int n0 = blockIdx.x * BNF;   // filter base
    const int m0 = blockIdx.y * BM;    // bt base
    const int variant = blockIdx.z >> 1;
    const int kbase = (blockIdx.z & 1) * KHALF;
    const __half* wmat = variant ? wc_h : ws_h;
    float* gout = g_buf[blockIdx.z];

    const int lane = tid & 31;
    const int warp = tid >> 5;
    const int wm = (warp & 1) * 64;
    const int wn = (warp >> 1) * 32;

    float acc[4][4][4];
    #pragma unroll
    for (int i = 0; i < 4; i++)
        #pragma unroll
        for (int j = 0; j < 4; j++)
            #pragma unroll
            for (int k = 0; k < 4; k++) acc[i][j][k] = 0.f;

    // loader: row = tid>>2 (0..63, +64), seg = tid&3 (16B each); 2 xfers/array
    const int lrow = tid >> 2;
    const int seg = tid & 3;
    const __half* ga = x_h  + (size_t)(m0 + lrow) * HWDIM + kbase + seg * 8;
    const __half* gb = wmat + (size_t)(n0 + lrow) * HWDIM + kbase + seg * 8;
    const unsigned lsm = smem_base + lrow * PADROWB + seg * 16;

    auto load_stage = [&](int kt, int slot) {
        const unsigned sb = lsm + slot * STG_BYTES;
        const __half* pa = ga + kt * KC;
        const __half* pb = gb + kt * KC;
        #pragma unroll
        for (int i = 0; i < 2; i++) {
            cp_async16(sb + OFF_A + i * 64 * PADROWB, pa + (size_t)i * 64 * HWDIM);
            cp_async16(sb + OFF_B + i * 64 * PADROWB, pb + (size_t)i * 64 * HWDIM);
        }
        asm volatile("cp.async.commit_group;\n");
    };

    // ldmatrix per-lane byte offsets within a stage
    const int mrow = wm + (lane & 7) + 8 * ((lane >> 3) & 1);
    const int akb  = (lane >> 4) * 16;
    unsigned aoff[4];
    #pragma unroll
    for (int mt = 0; mt < 4; mt++) aoff[mt] = (mrow + mt * 16) * PADROWB + akb;

    const int nrow = wn + (lane & 7) + 8 * (lane >> 4);
    const int bkb  = ((lane >> 3) & 1) * 16;
    unsigned boff[2];
    #pragma unroll
    for (int p = 0; p < 2; p++) boff[p] = (nrow + p * 16) * PADROWB + bkb;

    // prologue
    load_stage(0, 0);
    load_stage(1, 1);

    for (int kt = 0; kt < NCHUNK; kt++) {
        if (kt < NCHUNK - 1) asm volatile("cp.async.wait_group 1;\n");
        else                 asm volatile("cp.async.wait_group 0;\n");
        __syncthreads();
        if (kt + 2 < NCHUNK) load_stage(kt + 2, (kt + 2) % 3);

        const unsigned sb = smem_base + (kt % 3) * STG_BYTES;
        #pragma unroll
        for (int kk = 0; kk < 2; kk++) {
            const unsigned kb = kk * 32;
            uint32_t a[4][4], b[2][4];
            #pragma unroll
            for (int mt = 0; mt < 4; mt++) ldsm_x4(a[mt], sb + OFF_A + aoff[mt] + kb);
            #pragma unroll
            for (int p = 0; p < 2; p++) ldsm_x4(b[p], sb + OFF_B + boff[p] + kb);
            #pragma unroll
            for (int mt = 0; mt < 4; mt++)
                #pragma unroll
                for (int nt = 0; nt < 4; nt++)
                    mma_fp16(acc[mt][nt], a[mt], &b[nt >> 1][(nt & 1) * 2]);
        }
        __syncthreads();
    }

    // epilogue
    #pragma unroll
    for (int mt = 0; mt < 4; mt++) {
        #pragma unroll
        for (int nt = 0; nt < 4; nt++) {
            int m = m0 + wm + mt * 16 + (lane >> 2);
            int n = n0 + wn + nt * 8 + (lane & 3) * 2;
            *reinterpret_cast<float2*>(&gout[(size_t)m * NF + n]) =
                make_float2(acc[mt][nt][0], acc[mt][nt][1]);
            *reinterpret_cast<float2*>(&gout[(size_t)(m + 8) * NF + n]) =
                make_float2(acc[mt][nt][2], acc[mt][nt][3]);
        }
    }
}

// ---------------------------------------------------------------------------
// Kernel 2: sum split-K halves + depthwise temporal convs + energy.
// Ring-buffer sliding window, T split into 5 chunks of 48.
// ---------------------------------------------------------------------------
__global__ void __launch_bounds__(256)
temporal_kernel(const float* __restrict__ wt_sin_g,
                const float* __restrict__ wt_cos_g,
                float* __restrict__ out) {
    const int f = blockIdx.x * 256 + threadIdx.x;
    const int b = blockIdx.y;
    const int t0 = blockIdx.z * 48;

    float wts[TW], wtc[TW];
    #pragma unroll
    for (int j = 0; j < TW; j++) {
        wts[j] = wt_sin_g[f * TW + j];
        wtc[j] = wt_cos_g[f * TW + j];
    }

    const size_t base = (size_t)b * T_LEN * NF + f;
    const float* gs0 = g_buf[0] + base;
    const float* gs1 = g_buf[1] + base;
    const float* gc0 = g_buf[2] + base;
    const float* gc1 = g_buf[3] + base;
    float* op = out + base;

    float rs[TW], rc[TW];
    #pragma unroll
    for (int j = 0; j < TW; j++) {
        int t = t0 - 8 + j;
        int i = t & 15;
        rs[i] = (t >= 0) ? (gs0[t * NF] + gs1[t * NF]) : 0.f;
        rc[i] = (t >= 0) ? (gc0[t * NF] + gc1[t * NF]) : 0.f;
    }

    #pragma unroll 16
    for (int tt = 0; tt < 48; tt++) {
        const int t = t0 + tt;
        float t1 = 0.f, t2 = 0.f, t3 = 0.f, t4 = 0.f;
        #pragma unroll
        for (int j = 0; j < TW; j++) {
            int i = (tt - 8 + j) & 15;
            t1 += rs[i] * wtc[j];
            t2 += rc[i] * wts[j];
            t3 += rc[i] * wtc[j];
            t4 += rs[i] * wts[j];
        }
        float resp_s = t1 + t2;
        float resp_c = t3 - t4;
        float v = resp_s * resp_s + resp_c * resp_c;
        op[t * NF] = logf(sqrtf(v) + 1e-5f);

        int tn = t + 8;
        int i = tn & 15;
        rs[i] = (tn < T_LEN) ? (gs0[tn * NF] + gs1[tn * NF]) : 0.f;
        rc[i] = (tn < T_LEN) ? (gc0[tn * NF] + gc1[tn * NF]) : 0.f;
    }
}

extern "C" void kernel_launch(void* const* d_in, const int* in_sizes, int n_in,
                              void* d_out, int out_size) {
    const float* x       = (const float*)d_in[0];
    const float* w_s_sin = (const float*)d_in[1];
    const float* w_s_cos = (const float*)d_in[2];
    const float* w_t_sin = (const float*)d_in[3];
    const float* w_t_cos = (const float*)d_in[4];
    float* out = (float*)d_out;

    const int ntot = NX4 + 2 * NW4;
    f2h_all_kernel<<<(ntot + 255) / 256, 256>>>(x, w_s_sin, w_s_cos);

    cudaFuncSetAttribute(spatial_gemm_fp16,
                         cudaFuncAttributeMaxDynamicSharedMemorySize, SMEM_DYN);

    dim3 g1(NF / BNF, BT / BM, 4);     // (20, 15, 4) = 1200 CTAs, split-K x2
    spatial_gemm_fp16<<<g1, 256, SMEM_DYN>>>(0);

    dim3 g2(NF / 256, BATCH, T_LEN / 48);   // (10, 8, 5)
    temporal_kernel<<<g2, 256>>>(w_t_sin, w_t_cos, out);
}

// round 7
// speedup vs baseline: 1.2690x; 1.0135x over previous
#include <cuda_runtime.h>
#include <cuda_fp16.h>
#include <cstdint>

#define NF      2560
#define TW      16
#define HWDIM   9216
#define BT      1920
#define T_LEN   240
#define BATCH   8

#define BM      128     // bt rows per CTA (M)
#define BNF     128     // filters per CTA (N)
#define KC      32      // K elements per stage
#define NCHUNK  288     // HWDIM / KC
#define NSTAGE  4
#define PADROWB 80      // bytes per smem row (32 halves = 64B + 16B pad)
#define OFF_A   0
#define OFF_B   (128 * PADROWB)          // 10240
#define STG_BYTES (256 * PADROWB)        // 20480
#define SMEM_DYN  (NSTAGE * STG_BYTES)   // 81920

// fp16 copies of inputs (filled by convert kernel)
__device__ __half x_h[BT * HWDIM];
__device__ __half ws_h[NF * HWDIM];
__device__ __half wc_h[NF * HWDIM];
// intermediate g_sin / g_cos, layout [bt][f]
__device__ float g_buf0[BT * NF];
__device__ float g_buf1[BT * NF];

// ---------------------------------------------------------------------------
__device__ __forceinline__ unsigned smem_u32(const void* p) {
    return (unsigned)__cvta_generic_to_shared(p);
}
__device__ __forceinline__ void cp_async16(unsigned saddr, const void* gaddr) {
    asm volatile("cp.async.cg.shared.global [%0], [%1], 16;\n" :: "r"(saddr), "l"(gaddr));
}
__device__ __forceinline__ void ldsm_x4(uint32_t* r, unsigned addr) {
    asm volatile("ldmatrix.sync.aligned.m8n8.x4.shared.b16 {%0,%1,%2,%3}, [%4];"
                 : "=r"(r[0]), "=r"(r[1]), "=r"(r[2]), "=r"(r[3]) : "r"(addr));
}
__device__ __forceinline__ void mma_fp16(float* c, const uint32_t* a, const uint32_t* b) {
    asm volatile(
        "mma.sync.aligned.m16n8k16.row.col.f32.f16.f16.f32 "
        "{%0,%1,%2,%3}, {%4,%5,%6,%7}, {%8,%9}, {%0,%1,%2,%3};\n"
        : "+f"(c[0]), "+f"(c[1]), "+f"(c[2]), "+f"(c[3])
        : "r"(a[0]), "r"(a[1]), "r"(a[2]), "r"(a[3]), "r"(b[0]), "r"(b[1]));
}

// ---------------------------------------------------------------------------
// Kernel 0: fp32 -> fp16 conversion for x, w_s_sin, w_s_cos in ONE launch.
// ---------------------------------------------------------------------------
#define NX4 (BT * HWDIM / 4)
#define NW4 (NF * HWDIM / 4)
__global__ void __launch_bounds__(256)
f2h_all_kernel(const float* __restrict__ x,
               const float* __restrict__ wsin,
               const float* __restrict__ wcos) {
    int i = blockIdx.x * 256 + threadIdx.x;
    const float* src;
    __half* dst;
    int j;
    if (i < NX4)                 { src = x;    dst = x_h;  j = i; }
    else if (i < NX4 + NW4)      { src = wsin; dst = ws_h; j = i - NX4; }
    else if (i < NX4 + 2 * NW4)  { src = wcos; dst = wc_h; j = i - NX4 - NW4; }
    else return;
    float4 v = reinterpret_cast<const float4*>(src)[j];
    reinterpret_cast<__half2*>(dst)[2 * j]     = __floats2half2_rn(v.x, v.y);
    reinterpret_cast<__half2*>(dst)[2 * j + 1] = __floats2half2_rn(v.z, v.w);
}

// ---------------------------------------------------------------------------
// Kernel 1: spatial GEMM, fp16 mma.sync, KC=32, 4-stage cp.async (wait 2),
// ONE __syncthreads per K-chunk, 2 CTAs/SM.
//   g[m, f] = sum_k x[m,k] * w[f,k]
// Block tile 128(m) x 128(f), 256 threads, warp tile 64m x 32f.
// blockIdx.z: 0 -> ws_h -> g_buf0, 1 -> wc_h -> g_buf1.
// ---------------------------------------------------------------------------
__global__ void __launch_bounds__(256, 2)
spatial_gemm_fp16(int dummy) {
    extern __shared__ __align__(1024) char smem[];
    const unsigned smem_base = smem_u32(smem);
    const int tid = threadIdx.x;
    const int n0 = blockIdx.x * BNF;   // filter base
    const int m0 = blockIdx.y * BM;    // bt base
    const __half* wmat = blockIdx.z ? wc_h : ws_h;
    float* gout = blockIdx.z ? g_buf1 : g_buf0;

    const int lane = tid & 31;
    const int warp = tid >> 5;
    const int wm = (warp & 1) * 64;
    const int wn = (warp >> 1) * 32;

    float acc[4][4][4];
    #pragma unroll
    for (int i = 0; i < 4; i++)
        #pragma unroll
        for (int j = 0; j < 4; j++)
            #pragma unroll
            for (int k = 0; k < 4; k++) acc[i][j][k] = 0.f;

    // loader: row = tid>>2 (0..63, +64), seg = tid&3 (16B each); 2 xfers/array
    const int lrow = tid >> 2;
    const int seg = tid & 3;
    const __half* ga = x_h  + (size_t)(m0 + lrow) * HWDIM + seg * 8;
    const __half* gb = wmat + (size_t)(n0 + lrow) * HWDIM + seg * 8;
    const unsigned lsm = smem_base + lrow * PADROWB + seg * 16;

    auto load_stage = [&](int kt, int slot) {
        const unsigned sb = lsm + slot * STG_BYTES;
        const __half* pa = ga + kt * KC;
        const __half* pb = gb + kt * KC;
        #pragma unroll
        for (int i = 0; i < 2; i++) {
            cp_async16(sb + OFF_A + i * 64 * PADROWB, pa + (size_t)i * 64 * HWDIM);
            cp_async16(sb + OFF_B + i * 64 * PADROWB, pb + (size_t)i * 64 * HWDIM);
        }
        asm volatile("cp.async.commit_group;\n");
    };

    // ldmatrix per-lane byte offsets within a stage
    const int mrow = wm + (lane & 7) + 8 * ((lane >> 3) & 1);
    const int akb  = (lane >> 4) * 16;
    unsigned aoff[4];
    #pragma unroll
    for (int mt = 0; mt < 4; mt++) aoff[mt] = (mrow + mt * 16) * PADROWB + akb;

    const int nrow = wn + (lane & 7) + 8 * (lane >> 4);
    const int bkb  = ((lane >> 3) & 1) * 16;
    unsigned boff[2];
    #pragma unroll
    for (int p = 0; p < 2; p++) boff[p] = (nrow + p * 16) * PADROWB + bkb;

    // prologue: fill 3 of 4 stages
    load_stage(0, 0);
    load_stage(1, 1);
    load_stage(2, 2);

    for (int kt = 0; kt < NCHUNK; kt++) {
        if (kt < NCHUNK - 2)      asm volatile("cp.async.wait_group 2;\n");
        else if (kt == NCHUNK - 2) asm volatile("cp.async.wait_group 1;\n");
        else                       asm volatile("cp.async.wait_group 0;\n");
        __syncthreads();   // stage kt ready; all warps done with stage kt-1
        if (kt + 3 < NCHUNK) load_stage(kt + 3, (kt + 3) % NSTAGE);

        const unsigned sb = smem_base + (kt % NSTAGE) * STG_BYTES;

        // hoist ALL fragment loads (both k-halves) before the MMAs:
        // one scoreboard ramp per iteration instead of two
        uint32_t a[2][4][4], b[2][2][4];
        #pragma unroll
        for (int kk = 0; kk < 2; kk++) {
            const unsigned kb = kk * 32;
            #pragma unroll
            for (int mt = 0; mt < 4; mt++) ldsm_x4(a[kk][mt], sb + OFF_A + aoff[mt] + kb);
            #pragma unroll
            for (int p = 0; p < 2; p++)  ldsm_x4(b[kk][p], sb + OFF_B + boff[p] + kb);
        }
        #pragma unroll
        for (int kk = 0; kk < 2; kk++)
            #pragma unroll
            for (int mt = 0; mt < 4; mt++)
                #pragma unroll
                for (int nt = 0; nt < 4; nt++)
                    mma_fp16(acc[mt][nt], a[kk][mt], &b[kk][nt >> 1][(nt & 1) * 2]);
        // no bottom sync: next iter's top barrier is the WAR guard (loads at
        // iter kt+1 target slot (kt+4)%4 = kt%4 only AFTER that barrier, and
        // with 4 stages the overwritten buffer is 3 iterations stale)
    }

    // epilogue
    #pragma unroll
    for (int mt = 0; mt < 4; mt++) {
        #pragma unroll
        for (int nt = 0; nt < 4; nt++) {
            int m = m0 + wm + mt * 16 + (lane >> 2);
            int n = n0 + wn + nt * 8 + (lane & 3) * 2;
            *reinterpret_cast<float2*>(&gout[(size_t)m * NF + n]) =
                make_float2(acc[mt][nt][0], acc[mt][nt][1]);
            *reinterpret_cast<float2*>(&gout[(size_t)(m + 8) * NF + n]) =
                make_float2(acc[mt][nt][2], acc[mt][nt][3]);
        }
    }
}

// ---------------------------------------------------------------------------
// Kernel 2: depthwise temporal convs + energy. Ring-buffer sliding window,
// T split into 5 chunks of 48.
// ---------------------------------------------------------------------------
__global__ void __launch_bounds__(256)
temporal_kernel(const float* __restrict__ wt_sin_g,
                const float* __restrict__ wt_cos_g,
                float* __restrict__ out) {
    const int f = blockIdx.x * 256 + threadIdx.x;
    const int b = blockIdx.y;
    const int t0 = blockIdx.z * 48;

    float wts[TW], wtc[TW];
    #pragma unroll
    for (int j = 0; j < TW; j++) {
        wts[j] = wt_sin_g[f * TW + j];
        wtc[j] = wt_cos_g[f * TW + j];
    }

    const float* gs = g_buf0 + (size_t)b * T_LEN * NF + f;
    const float* gc = g_buf1 + (size_t)b * T_LEN * NF + f;
    float* op = out + (size_t)b * T_LEN * NF + f;

    float rs[TW], rc[TW];
    #pragma unroll
    for (int j = 0; j < TW; j++) {
        int t = t0 - 8 + j;
        int i = t & 15;
        rs[i] = (t >= 0) ? gs[t * NF] : 0.f;
        rc[i] = (t >= 0) ? gc[t * NF] : 0.f;
    }

    #pragma unroll 16
    for (int tt = 0; tt < 48; tt++) {
        const int t = t0 + tt;
        float t1 = 0.f, t2 = 0.f, t3 = 0.f, t4 = 0.f;
        #pragma unroll
        for (int j = 0; j < TW; j++) {
            int i = (tt - 8 + j) & 15;
            t1 += rs[i] * wtc[j];
            t2 += rc[i] * wts[j];
            t3 += rc[i] * wtc[j];
            t4 += rs[i] * wts[j];
        }
        float resp_s = t1 + t2;
        float resp_c = t3 - t4;
        float v = resp_s * resp_s + resp_c * resp_c;
        op[t * NF] = logf(sqrtf(v) + 1e-5f);

        int tn = t + 8;
        int i = tn & 15;
        rs[i] = (tn < T_LEN) ? gs[tn * NF] : 0.f;
        rc[i] = (tn < T_LEN) ? gc[tn * NF] : 0.f;
    }
}

extern "C" void kernel_launch(void* const* d_in, const int* in_sizes, int n_in,
                              void* d_out, int out_size) {
    const float* x       = (const float*)d_in[0];
    const float* w_s_sin = (const float*)d_in[1];
    const float* w_s_cos = (const float*)d_in[2];
    const float* w_t_sin = (const float*)d_in[3];
    const float* w_t_cos = (const float*)d_in[4];
    float* out = (float*)d_out;

    const int ntot = NX4 + 2 * NW4;
    f2h_all_kernel<<<(ntot + 255) / 256, 256>>>(x, w_s_sin, w_s_cos);

    cudaFuncSetAttribute(spatial_gemm_fp16,
                         cudaFuncAttributeMaxDynamicSharedMemorySize, SMEM_DYN);

    dim3 g1(NF / BNF, BT / BM, 2);     // (20, 15, 2) = 600 CTAs, 2/SM
    spatial_gemm_fp16<<<g1, 256, SMEM_DYN>>>(0);

    dim3 g2(NF / 256, BATCH, T_LEN / 48);   // (10, 8, 5)
    temporal_kernel<<<g2, 256>>>(w_t_sin, w_t_cos, out);
}